// round 16
// baseline (speedup 1.0000x reference)
#include <cuda_runtime.h>
#include <cuda_fp16.h>
#include <cstdint>
#include <float.h>

#define NPTS 131072
#define KC   512
#define DD   256
#define NSLOT 8   // 8 colblocks of 64 (mma) / 4x{real,sentinel} (ffma fallback)

// ================= helpers =================
__device__ __forceinline__ uint32_t smem_u32(const void* p) {
    uint32_t a;
    asm("{ .reg .u64 t; cvta.to.shared.u64 t, %1; cvt.u32.u64 %0, t; }" : "=r"(a) : "l"(p));
    return a;
}
#define CP_ASYNC16(dst, src) \
    asm volatile("cp.async.cg.shared.global [%0], [%1], 16;" :: "r"(dst), "l"(src) : "memory")
#define CP_COMMIT() asm volatile("cp.async.commit_group;" ::: "memory")
#define CP_WAIT(n)  asm volatile("cp.async.wait_group %0;" :: "n"(n) : "memory")

#define LDSM_X4(r, addr) \
    asm volatile("ldmatrix.sync.aligned.m8n8.x4.shared.b16 {%0,%1,%2,%3}, [%4];" \
        : "=r"((r)[0]), "=r"((r)[1]), "=r"((r)[2]), "=r"((r)[3]) : "r"(addr))

__device__ __forceinline__ void mma16816(float* d, const uint32_t* a, const uint32_t* b) {
    asm volatile(
        "mma.sync.aligned.m16n8k16.row.col.f32.f16.f16.f32 "
        "{%0,%1,%2,%3}, {%4,%5,%6,%7}, {%8,%9}, {%0,%1,%2,%3};"
        : "+f"(d[0]), "+f"(d[1]), "+f"(d[2]), "+f"(d[3])
        : "r"(a[0]), "r"(a[1]), "r"(a[2]), "r"(a[3]), "r"(b[0]), "r"(b[1]));
}
__device__ __forceinline__ bool vi_lt(float av, int ai, float bv, int bi) {
    return (av < bv) || (av == bv && ai < bi);
}

// ================= scratch =================
__device__ __half g_xh[(size_t)NPTS * DD];
__device__ __half g_ch[KC * DD];
__device__ float g_c2f[KC];
__device__ float g_pv1[NSLOT * NPTS];
__device__ float g_pv2[NSLOT * NPTS];
__device__ int   g_pi1[NSLOT * NPTS];
__device__ int   g_pi2[NSLOT * NPTS];
__device__ int   g_i1[NPTS];
__device__ int   g_i2[NPTS];
__device__ float g_v1f[NPTS];
__device__ float g_v2f[NPTS];
__device__ int   g_assign[NPTS];
__device__ int   g_counts[KC];
__device__ int   g_offs[KC];
__device__ int   g_cursor[KC];
__device__ int   g_order[NPTS];
__device__ int   g_queue[NPTS];
__device__ int   g_qcnt;
__device__ int   g_fb;
__device__ float g_dummy_kd[KC * DD];
__device__ float g_dummy_n[NPTS];

// ================= c2 + zero (mma stays the 4th launch -> ncu slot) ============
__global__ void c2z_kernel(const float* __restrict__ cent) {
    int k = blockIdx.x;
    int t = threadIdx.x;  // 64
    if (t == 0) g_counts[k] = 0;
    if (k == 0 && t == 0) { g_fb = 0; g_qcnt = 0; }
    double s = 0.0;
    #pragma unroll
    for (int d = t; d < DD; d += 64) {
        double v = (double)cent[k * DD + d];
        s += v * v;
    }
    __shared__ double sh[64];
    sh[t] = s;
    __syncthreads();
    if (t < 32) {
        double v = sh[t] + sh[t + 32];
        #pragma unroll
        for (int o = 16; o; o >>= 1) v += __shfl_xor_sync(0xffffffffu, v, o);
        if (t == 0) g_c2f[k] = (float)v;
    }
}

// x -> fp16
__global__ void convert_x_kernel(const float* __restrict__ x) {
    size_t i = ((size_t)blockIdx.x * 256 + threadIdx.x) * 4;
    if (i >= (size_t)NPTS * DD) return;
    float4 v = *(const float4*)(x + i);
    ((__half2*)(g_xh + i))[0] = __floats2half2_rn(v.x, v.y);
    ((__half2*)(g_xh + i))[1] = __floats2half2_rn(v.z, v.w);
}
// centroids -> fp16
__global__ void convert_c_kernel(const float* __restrict__ c) {
    size_t i = ((size_t)blockIdx.x * 256 + threadIdx.x) * 4;
    if (i >= (size_t)KC * DD) return;
    float4 v = *(const float4*)(c + i);
    ((__half2*)(g_ch + i))[0] = __floats2half2_rn(v.x, v.y);
    ((__half2*)(g_ch + i))[1] = __floats2half2_rn(v.z, v.w);
}

// ================= MMA distance GEMM: CTA 128x64, 3 CTAs/SM ====================
// grid (1024, 8). 8 warps, each owns 16 rows x 64 cols. acc = 32 regs/thread.
// Double-buffered 27.6KB stages (A 128x64h + B 64x64h), prefetch 1 ahead.
#define PITCH 144
#define STG   27648                 // A(18432) + B(9216)
#define SM_C2 (2 * STG)             // 55296
#define SM_TOTAL (SM_C2 + 256)      // 55552
#define NCHUNK 4

__device__ __forceinline__ void stage_chunk(uint32_t sbase, int s,
                                            int rowTile, int colTile, int tid) {
    const int k0 = s * 64;
    uint32_t abase = sbase + (s & 1) * STG;
    uint32_t bbase = abase + 18432;
    #pragma unroll
    for (int i = 0; i < 4; i++) {
        int u = tid + i * 256;          // [0,1024): 128 rows x 8 16B-units
        int row = u >> 3, c16 = u & 7;
        CP_ASYNC16(abase + row * PITCH + c16 * 16,
                   g_xh + (size_t)(rowTile + row) * DD + k0 + c16 * 8);
    }
    #pragma unroll
    for (int i = 0; i < 2; i++) {
        int u = tid + i * 256;          // [0,512): 64 rows x 8 16B-units
        int row = u >> 3, c16 = u & 7;
        CP_ASYNC16(bbase + row * PITCH + c16 * 16,
                   g_ch + (size_t)(colTile + row) * DD + k0 + c16 * 8);
    }
    CP_COMMIT();
}

__global__ __launch_bounds__(256, 3) void mma_top2_kernel() {
    extern __shared__ char smem[];
    const uint32_t sbase = smem_u32(smem);
    const int tid = threadIdx.x;
    const int wid = tid >> 5;       // warpM 0-7: 16-row strip
    const int lane = tid & 31;
    const int rowTile = blockIdx.x * 128;
    const int colTile = blockIdx.y * 64;
    const int tg = lane & 3;

    float* c2s = (float*)(smem + SM_C2);
    if (tid < 64) c2s[tid] = g_c2f[colTile + tid];

    const int rowA = (lane & 7) + (((lane >> 3) & 1) << 3);
    const int koA  = ((lane >> 4) & 1) * 16;
    const int rowB = (lane & 7) + (((lane >> 4) & 1) << 3);
    const int koB  = ((lane >> 3) & 1) * 16;

    float acc[8][4];
    #pragma unroll
    for (int nt = 0; nt < 8; nt++)
        #pragma unroll
        for (int e = 0; e < 4; e++) acc[nt][e] = 0.0f;

    stage_chunk(sbase, 0, rowTile, colTile, tid);

    #pragma unroll 1
    for (int c = 0; c < NCHUNK; c++) {
        CP_WAIT(0);                  // chunk c landed (c+1 not yet issued)
        __syncthreads();             // visible to all warps
        if (c + 1 < NCHUNK)
            stage_chunk(sbase, c + 1, rowTile, colTile, tid);  // overlaps compute

        uint32_t abase = sbase + (c & 1) * STG;
        uint32_t bbase = abase + 18432;

        #pragma unroll
        for (int ks = 0; ks < 4; ks++) {
            uint32_t a[4];
            LDSM_X4(a, abase + (wid * 16 + rowA) * PITCH + ks * 32 + koA);
            uint32_t b[8][2];
            #pragma unroll
            for (int nt2 = 0; nt2 < 4; nt2++) {
                uint32_t t[4];
                LDSM_X4(t, bbase + (nt2 * 16 + rowB) * PITCH + ks * 32 + koB);
                b[2 * nt2][0]     = t[0];
                b[2 * nt2][1]     = t[1];
                b[2 * nt2 + 1][0] = t[2];
                b[2 * nt2 + 1][1] = t[3];
            }
            #pragma unroll
            for (int nt = 0; nt < 8; nt++)
                mma16816(acc[nt], a, b[nt]);
        }
        __syncthreads();             // reads of chunk c done -> buffer reusable
    }

    // epilogue: rows wid*16 + g (rr=0) / +8 (rr=1); cols nt*8 + 2tg + e (64 local)
    const int g = lane >> 2;
    const int slot = blockIdx.y;
    #pragma unroll
    for (int rr = 0; rr < 2; rr++) {
        float v1 = FLT_MAX, v2 = FLT_MAX;
        int i1 = 0x7fffffff, i2 = 0x7fffffff;
        #pragma unroll
        for (int nt = 0; nt < 8; nt++) {
            #pragma unroll
            for (int e = 0; e < 2; e++) {
                int colL = nt * 8 + tg * 2 + e;
                float s = c2s[colL] - 2.0f * acc[nt][rr * 2 + e];
                int col = colTile + colL;
                if (vi_lt(s, col, v1, i1)) { v2 = v1; i2 = i1; v1 = s; i1 = col; }
                else if (vi_lt(s, col, v2, i2)) { v2 = s; i2 = col; }
            }
        }
        #pragma unroll
        for (int o = 1; o <= 2; o <<= 1) {
            float w1 = __shfl_xor_sync(0xffffffffu, v1, o);
            float w2 = __shfl_xor_sync(0xffffffffu, v2, o);
            int   j1 = __shfl_xor_sync(0xffffffffu, i1, o);
            int   j2 = __shfl_xor_sync(0xffffffffu, i2, o);
            if (vi_lt(w1, j1, v1, i1)) {
                if (vi_lt(v1, i1, w2, j2)) { v2 = v1; i2 = i1; }
                else                        { v2 = w2; i2 = j2; }
                v1 = w1; i1 = j1;
            } else if (vi_lt(w1, j1, v2, i2)) {
                v2 = w1; i2 = j1;
            }
        }
        if (tg == 0) {
            int rowL = wid * 16 + rr * 8 + g;
            size_t off = (size_t)slot * NPTS + rowTile + rowL;
            g_pv1[off] = v1; g_pi1[off] = i1;
            g_pv2[off] = v2; g_pi2[off] = i2;
        }
    }
}

// ================= FFMA fallback (proven path, gated on g_fb) =================
__global__ __launch_bounds__(256) void ffma_top2_kernel(
    const float* __restrict__ x, const float* __restrict__ cent)
{
    if (!g_fb) return;
    __shared__ __align__(16) float As[32][128];
    __shared__ __align__(16) float Bs[32][128];

    const int tid = threadIdx.x;
    const int tx = tid & 15;
    const int ty = tid >> 4;
    const int rowTile = blockIdx.x * 128;
    const int colTile = blockIdx.y * 128;

    float acc[8][8];
    #pragma unroll
    for (int i = 0; i < 8; i++)
        #pragma unroll
        for (int j = 0; j < 8; j++) acc[i][j] = 0.0f;

    for (int kk = 0; kk < DD; kk += 32) {
        #pragma unroll
        for (int i = 0; i < 4; i++) {
            int l = tid + i * 256;
            int row = l >> 3;
            int c4 = l & 7;
            float4 va = *(const float4*)(x + (size_t)(rowTile + row) * DD + kk + c4 * 4);
            As[c4 * 4 + 0][row] = va.x;
            As[c4 * 4 + 1][row] = va.y;
            As[c4 * 4 + 2][row] = va.z;
            As[c4 * 4 + 3][row] = va.w;
            float4 vb = *(const float4*)(cent + (size_t)(colTile + row) * DD + kk + c4 * 4);
            Bs[c4 * 4 + 0][row] = vb.x;
            Bs[c4 * 4 + 1][row] = vb.y;
            Bs[c4 * 4 + 2][row] = vb.z;
            Bs[c4 * 4 + 3][row] = vb.w;
        }
        __syncthreads();
        #pragma unroll
        for (int k = 0; k < 32; k++) {
            float a[8], b[8];
            *(float4*)&a[0] = *(const float4*)&As[k][ty * 8];
            *(float4*)&a[4] = *(const float4*)&As[k][ty * 8 + 4];
            *(float4*)&b[0] = *(const float4*)&Bs[k][tx * 8];
            *(float4*)&b[4] = *(const float4*)&Bs[k][tx * 8 + 4];
            #pragma unroll
            for (int i = 0; i < 8; i++)
                #pragma unroll
                for (int j = 0; j < 8; j++)
                    acc[i][j] += a[i] * b[j];
        }
        __syncthreads();
    }

    float c2r[8];
    #pragma unroll
    for (int j = 0; j < 8; j++) c2r[j] = g_c2f[colTile + tx * 8 + j];

    #pragma unroll
    for (int i = 0; i < 8; i++) {
        float v1 = FLT_MAX, v2 = FLT_MAX;
        int i1 = 0x7fffffff, i2 = 0x7fffffff;
        #pragma unroll
        for (int j = 0; j < 8; j++) {
            int col = colTile + tx * 8 + j;
            float s = c2r[j] - 2.0f * acc[i][j];
            if (vi_lt(s, col, v1, i1)) { v2 = v1; i2 = i1; v1 = s; i1 = col; }
            else if (vi_lt(s, col, v2, i2)) { v2 = s; i2 = col; }
        }
        #pragma unroll
        for (int o = 8; o; o >>= 1) {
            float w1 = __shfl_xor_sync(0xffffffffu, v1, o, 16);
            float w2 = __shfl_xor_sync(0xffffffffu, v2, o, 16);
            int   j1 = __shfl_xor_sync(0xffffffffu, i1, o, 16);
            int   j2 = __shfl_xor_sync(0xffffffffu, i2, o, 16);
            if (vi_lt(w1, j1, v1, i1)) {
                if (vi_lt(v1, i1, w2, j2)) { v2 = v1; i2 = i1; }
                else                        { v2 = w2; i2 = j2; }
                v1 = w1; i1 = j1;
            } else if (vi_lt(w1, j1, v2, i2)) {
                v2 = w1; i2 = j1;
            }
        }
        if (tx == 0) {
            int r = rowTile + ty * 8 + i;
            size_t off0 = (size_t)(blockIdx.y * 2) * NPTS + r;
            size_t off1 = (size_t)(blockIdx.y * 2 + 1) * NPTS + r;
            g_pv1[off0] = v1; g_pi1[off0] = i1;
            g_pv2[off0] = v2; g_pi2[off0] = i2;
            g_pv1[off1] = FLT_MAX; g_pi1[off1] = 0x7fffffff;
            g_pv2[off1] = FLT_MAX; g_pi2[off1] = 0x7fffffff;
        }
    }
}

// ================= reduce NSLOT partials -> global top-2 =================
__global__ void reduce_top2_kernel(int gated) {
    if (gated && !g_fb) return;
    int n = blockIdx.x * 256 + threadIdx.x;
    if (n >= NPTS) return;
    float v1 = g_pv1[n], v2 = g_pv2[n];
    int i1 = g_pi1[n], i2 = g_pi2[n];
    #pragma unroll
    for (int p = 1; p < NSLOT; p++) {
        size_t off = (size_t)p * NPTS + n;
        float w1 = g_pv1[off], w2 = g_pv2[off];
        int j1 = g_pi1[off], j2 = g_pi2[off];
        if (vi_lt(w1, j1, v1, i1)) {
            if (vi_lt(v1, i1, w2, j2)) { v2 = v1; i2 = i1; }
            else                        { v2 = w2; i2 = j2; }
            v1 = w1; i1 = j1;
        } else if (vi_lt(w1, j1, v2, i2)) {
            v2 = w1; i2 = j1;
        }
    }
    g_i1[n] = i1;
    g_i2[n] = i2;
    g_v1f[n] = v1;
    g_v2f[n] = v2;
}

// ================= validate sampled candidates (sets g_fb) =================
__global__ void validate_kernel(const float* __restrict__ x,
                                const float* __restrict__ cent)
{
    int w = (blockIdx.x * blockDim.x + threadIdx.x) >> 5;
    int lane = threadIdx.x & 31;
    if (w >= 256) return;
    int n = w * 512 + (w & 127);
    int i1 = g_i1[n], i2 = g_i2[n];
    if ((unsigned)i1 >= KC || (unsigned)i2 >= KC) {
        if (lane == 0) g_fb = 1;
        return;
    }
    const float4* xr = (const float4*)(x + (size_t)n * DD);
    float4 xa = xr[lane], xb = xr[lane + 32];
    const float4* ca4 = (const float4*)(cent + (size_t)i1 * DD);
    float4 ca = ca4[lane], cb = ca4[lane + 32];
    const float4* da4 = (const float4*)(cent + (size_t)i2 * DD);
    float4 da = da4[lane], db = da4[lane + 32];
    float d1 = xa.x * ca.x + xa.y * ca.y + xa.z * ca.z + xa.w * ca.w +
               xb.x * cb.x + xb.y * cb.y + xb.z * cb.z + xb.w * cb.w;
    float d2 = xa.x * da.x + xa.y * da.y + xa.z * da.z + xa.w * da.w +
               xb.x * db.x + xb.y * db.y + xb.z * db.z + xb.w * db.w;
    #pragma unroll
    for (int o = 16; o; o >>= 1) {
        d1 += __shfl_xor_sync(0xffffffffu, d1, o);
        d2 += __shfl_xor_sync(0xffffffffu, d2, o);
    }
    if (lane == 0) {
        float s1 = g_c2f[i1] - 2.0f * d1;
        float s2 = g_c2f[i2] - 2.0f * d2;
        if (fabsf(s1 - g_v1f[n]) > 0.02f || fabsf(s2 - g_v2f[n]) > 0.02f) g_fb = 1;
    }
}

// ================= fast assign: clear-gap points skip the fp64 replay ==========
__global__ void assign_fast_kernel(float* __restrict__ out_assign) {
    int n = blockIdx.x * 256 + threadIdx.x;
    if (n >= NPTS) return;
    float v1 = g_v1f[n], v2 = g_v2f[n];
    int i1 = g_i1[n];
    if (v2 - v1 > 4e-3f) {
        g_assign[n] = i1;
        out_assign[n] = (float)i1;
        atomicAdd(&g_counts[i1], 1);
    } else {
        int pos = atomicAdd(&g_qcnt, 1);
        g_queue[pos] = n;
    }
}

// ================= fp64 refine on queued points only =================
__global__ void refine_queue_kernel(const float* __restrict__ x,
                                    const float* __restrict__ cent,
                                    float* __restrict__ out_assign)
{
    int warp = (blockIdx.x * blockDim.x + threadIdx.x) >> 5;
    int lane = threadIdx.x & 31;
    int nwarps = (gridDim.x * blockDim.x) >> 5;
    int qn = g_qcnt;

    for (int qi = warp; qi < qn; qi += nwarps) {
        int n = g_queue[qi];
        int i1 = g_i1[n], i2 = g_i2[n];

        const float4* xr = (const float4*)(x + (size_t)n * DD);
        float4 xa = xr[lane], xb = xr[lane + 32];
        const float4* c1 = (const float4*)(cent + (size_t)i1 * DD);
        float4 ca = c1[lane], cb = c1[lane + 32];
        const float4* c2p = (const float4*)(cent + (size_t)i2 * DD);
        float4 da = c2p[lane], db = c2p[lane + 32];

        double x2 = (double)xa.x * xa.x + (double)xa.y * xa.y +
                    (double)xa.z * xa.z + (double)xa.w * xa.w +
                    (double)xb.x * xb.x + (double)xb.y * xb.y +
                    (double)xb.z * xb.z + (double)xb.w * xb.w;
        double m1 = (double)xa.x * ca.x + (double)xa.y * ca.y +
                    (double)xa.z * ca.z + (double)xa.w * ca.w +
                    (double)xb.x * cb.x + (double)xb.y * cb.y +
                    (double)xb.z * cb.z + (double)xb.w * cb.w;
        double m2 = (double)xa.x * da.x + (double)xa.y * da.y +
                    (double)xa.z * da.z + (double)xa.w * da.w +
                    (double)xb.x * db.x + (double)xb.y * db.y +
                    (double)xb.z * db.z + (double)xb.w * db.w;

        #pragma unroll
        for (int o = 16; o; o >>= 1) {
            x2 += __shfl_xor_sync(0xffffffffu, x2, o);
            m1 += __shfl_xor_sync(0xffffffffu, m1, o);
            m2 += __shfl_xor_sync(0xffffffffu, m2, o);
        }

        if (lane == 0) {
            float x2f = (float)x2, m1f = (float)m1, m2f = (float)m2;
            float d2a = __fadd_rn(__fsub_rn(x2f, __fmul_rn(2.0f, m1f)), g_c2f[i1]);
            float d2b = __fadd_rn(__fsub_rn(x2f, __fmul_rn(2.0f, m2f)), g_c2f[i2]);
            d2a = fmaxf(d2a, 0.0f);
            d2b = fmaxf(d2b, 0.0f);
            float dsa = __fsqrt_rn(d2a);
            float dsb = __fsqrt_rn(d2b);
            int win;
            if (dsa < dsb)      win = i1;
            else if (dsb < dsa) win = i2;
            else                win = (i1 < i2) ? i1 : i2;
            g_assign[n] = win;
            out_assign[n] = (float)win;
            atomicAdd(&g_counts[win], 1);
        }
    }
}

// ================= binning: scan counts -> per-cluster lists =================
__global__ void offsets_kernel() {
    __shared__ int sh[KC];
    int t = threadIdx.x;  // 512
    int c = g_counts[t];
    sh[t] = c;
    __syncthreads();
    #pragma unroll
    for (int o = 1; o < KC; o <<= 1) {
        int v = (t >= o) ? sh[t - o] : 0;
        __syncthreads();
        sh[t] += v;
        __syncthreads();
    }
    int excl = sh[t] - c;
    g_offs[t] = excl;
    g_cursor[t] = excl;
}

__global__ void fill_kernel() {
    int n = blockIdx.x * 256 + threadIdx.x;
    if (n >= NPTS) return;
    int a = g_assign[n];
    int pos = atomicAdd(&g_cursor[a], 1);
    g_order[pos] = n;
}

// ================= per-cluster sum (no atomics) + finalize =================
__global__ void sum_finalize_kernel(const float* __restrict__ x,
                                    const float* __restrict__ cent,
                                    float* __restrict__ out_old,
                                    float* __restrict__ out_new)
{
    int k = blockIdx.x;
    int d = threadIdx.x;  // 256
    int beg = g_offs[k];
    int cnt = g_counts[k];

    float acc = 0.0f;
    int i = 0;
    for (; i + 4 <= cnt; i += 4) {
        int p0 = g_order[beg + i];
        int p1 = g_order[beg + i + 1];
        int p2 = g_order[beg + i + 2];
        int p3 = g_order[beg + i + 3];
        acc += x[(size_t)p0 * DD + d];
        acc += x[(size_t)p1 * DD + d];
        acc += x[(size_t)p2 * DD + d];
        acc += x[(size_t)p3 * DD + d];
    }
    for (; i < cnt; i++) {
        int p = g_order[beg + i];
        acc += x[(size_t)p * DD + d];
    }

    int idx = k * DD + d;
    float oldv = cent[idx];
    out_old[idx] = oldv;
    out_new[idx] = (cnt > 0) ? (acc / (float)cnt) : oldv;
}

// ================= launch =================
extern "C" void kernel_launch(void* const* d_in, const int* in_sizes, int n_in,
                              void* d_out, int out_size) {
    const float* x = (const float*)d_in[0];
    const float* cent = (const float*)d_in[1];
    float* out = (float*)d_out;

    float* out_old;
    float* out_assign;
    float* out_new;
    float* p_dummy_kd = nullptr;
    float* p_dummy_n = nullptr;
    cudaGetSymbolAddress((void**)&p_dummy_kd, g_dummy_kd);
    cudaGetSymbolAddress((void**)&p_dummy_n, g_dummy_n);

    if (out_size >= KC * DD + NPTS + KC * DD) {
        out_old = out;
        out_assign = out + KC * DD;
        out_new = out_assign + NPTS;
    } else if (out_size == NPTS + KC * DD) {
        out_old = p_dummy_kd;
        out_assign = out;
        out_new = out + NPTS;
    } else if (out_size == KC * DD) {
        out_old = p_dummy_kd;
        out_assign = p_dummy_n;
        out_new = out;
    } else {
        out_old = p_dummy_kd;
        out_assign = p_dummy_n;
        out_new = p_dummy_kd;
    }

    cudaFuncSetAttribute(mma_top2_kernel,
                         cudaFuncAttributeMaxDynamicSharedMemorySize, SM_TOTAL);

    c2z_kernel<<<KC, 64>>>(cent);                                  // 1
    convert_x_kernel<<<(NPTS * (DD / 4)) / 256, 256>>>(x);         // 2
    convert_c_kernel<<<(KC * (DD / 4) + 255) / 256, 256>>>(cent);  // 3
    {
        dim3 grid(NPTS / 128, 8);
        mma_top2_kernel<<<grid, 256, SM_TOTAL>>>();                // 4 (ncu slot)
    }
    reduce_top2_kernel<<<NPTS / 256, 256>>>(0);                    // 5
    validate_kernel<<<32, 256>>>(x, cent);                         // 6
    {
        dim3 grid(NPTS / 128, 4);
        ffma_top2_kernel<<<grid, 256>>>(x, cent);                  // 7 (dormant)
    }
    reduce_top2_kernel<<<NPTS / 256, 256>>>(1);                    // 8 (gated)
    assign_fast_kernel<<<NPTS / 256, 256>>>(out_assign);           // 9
    refine_queue_kernel<<<256, 256>>>(x, cent, out_assign);        // 10
    offsets_kernel<<<1, KC>>>();                                   // 11
    fill_kernel<<<NPTS / 256, 256>>>();                            // 12
    sum_finalize_kernel<<<KC, DD>>>(x, cent, out_old, out_new);    // 13
}

// round 17
// speedup vs baseline: 1.0622x; 1.0622x over previous
#include <cuda_runtime.h>
#include <cuda_fp16.h>
#include <cstdint>
#include <float.h>

#define NPTS 131072
#define KC   512
#define DD   256
#define NSLOT 8   // 4 colblocks x 2 warpN halves

// ================= helpers =================
__device__ __forceinline__ uint32_t smem_u32(const void* p) {
    uint32_t a;
    asm("{ .reg .u64 t; cvta.to.shared.u64 t, %1; cvt.u32.u64 %0, t; }" : "=r"(a) : "l"(p));
    return a;
}
#define CP_ASYNC16(dst, src) \
    asm volatile("cp.async.cg.shared.global [%0], [%1], 16;" :: "r"(dst), "l"(src) : "memory")
#define CP_COMMIT() asm volatile("cp.async.commit_group;" ::: "memory")
#define CP_WAIT(n)  asm volatile("cp.async.wait_group %0;" :: "n"(n) : "memory")

#define LDSM_X4(r, addr) \
    asm volatile("ldmatrix.sync.aligned.m8n8.x4.shared.b16 {%0,%1,%2,%3}, [%4];" \
        : "=r"((r)[0]), "=r"((r)[1]), "=r"((r)[2]), "=r"((r)[3]) : "r"(addr))

__device__ __forceinline__ void mma16816(float* d, const uint32_t* a, const uint32_t* b) {
    asm volatile(
        "mma.sync.aligned.m16n8k16.row.col.f32.f16.f16.f32 "
        "{%0,%1,%2,%3}, {%4,%5,%6,%7}, {%8,%9}, {%0,%1,%2,%3};"
        : "+f"(d[0]), "+f"(d[1]), "+f"(d[2]), "+f"(d[3])
        : "r"(a[0]), "r"(a[1]), "r"(a[2]), "r"(a[3]), "r"(b[0]), "r"(b[1]));
}
__device__ __forceinline__ bool vi_lt(float av, int ai, float bv, int bi) {
    return (av < bv) || (av == bv && ai < bi);
}

// ================= scratch =================
__device__ __half g_xh[(size_t)NPTS * DD];
__device__ __half g_ch[KC * DD];
__device__ float g_c2f[KC];
__device__ float g_pv1[NSLOT * NPTS];
__device__ float g_pv2[NSLOT * NPTS];
__device__ int   g_pi1[NSLOT * NPTS];
__device__ int   g_pi2[NSLOT * NPTS];
__device__ int   g_i1[NPTS];
__device__ int   g_i2[NPTS];
__device__ int   g_assign[NPTS];
__device__ int   g_counts[KC];
__device__ int   g_offs[KC];
__device__ int   g_cursor[KC];
__device__ int   g_order[NPTS];
__device__ int   g_queue[NPTS];
__device__ int   g_qcnt;
__device__ float g_dummy_kd[KC * DD];
__device__ float g_dummy_n[NPTS];

// ================= c2 + zero (mma stays the 4th launch -> ncu slot) ============
__global__ void c2z_kernel(const float* __restrict__ cent) {
    int k = blockIdx.x;
    int t = threadIdx.x;  // 64
    if (t == 0) g_counts[k] = 0;
    if (k == 0 && t == 0) g_qcnt = 0;
    double s = 0.0;
    #pragma unroll
    for (int d = t; d < DD; d += 64) {
        double v = (double)cent[k * DD + d];
        s += v * v;
    }
    __shared__ double sh[64];
    sh[t] = s;
    __syncthreads();
    if (t < 32) {
        double v = sh[t] + sh[t + 32];
        #pragma unroll
        for (int o = 16; o; o >>= 1) v += __shfl_xor_sync(0xffffffffu, v, o);
        if (t == 0) g_c2f[k] = (float)v;
    }
}

// x -> fp16
__global__ void convert_x_kernel(const float* __restrict__ x) {
    size_t i = ((size_t)blockIdx.x * 256 + threadIdx.x) * 4;
    if (i >= (size_t)NPTS * DD) return;
    float4 v = *(const float4*)(x + i);
    ((__half2*)(g_xh + i))[0] = __floats2half2_rn(v.x, v.y);
    ((__half2*)(g_xh + i))[1] = __floats2half2_rn(v.z, v.w);
}
// centroids -> fp16
__global__ void convert_c_kernel(const float* __restrict__ c) {
    size_t i = ((size_t)blockIdx.x * 256 + threadIdx.x) * 4;
    if (i >= (size_t)KC * DD) return;
    float4 v = *(const float4*)(c + i);
    ((__half2*)(g_ch + i))[0] = __floats2half2_rn(v.x, v.y);
    ((__half2*)(g_ch + i))[1] = __floats2half2_rn(v.z, v.w);
}

// ================= MMA distance GEMM (R15 config: best measured) ===============
// CTA 128x128, 8 warps 4x2 (warp tile 32x64), 2 CTAs/SM, 3-stage ring.
#define PITCH 144
#define STAGE_BYTES 36864          // A(18432) + B(18432)
#define SM_C2 (3 * STAGE_BYTES)    // 110592
#define SM_TOTAL (SM_C2 + 512)     // 111104
#define NCHUNK 4

__device__ __forceinline__ void stage_chunk(uint32_t sbase, int s,
                                            int rowTile, int colTile, int tid) {
    const int k0 = s * 64;
    uint32_t abase = sbase + (s % 3) * STAGE_BYTES;
    uint32_t bbase = abase + 18432;
    #pragma unroll
    for (int i = 0; i < 4; i++) {
        int u = tid + i * 256;
        int row = u >> 3, c16 = u & 7;
        CP_ASYNC16(abase + row * PITCH + c16 * 16,
                   g_xh + (size_t)(rowTile + row) * DD + k0 + c16 * 8);
        CP_ASYNC16(bbase + row * PITCH + c16 * 16,
                   g_ch + (size_t)(colTile + row) * DD + k0 + c16 * 8);
    }
    CP_COMMIT();
}

__global__ __launch_bounds__(256, 2) void mma_top2_kernel() {
    extern __shared__ char smem[];
    const uint32_t sbase = smem_u32(smem);
    const int tid = threadIdx.x;
    const int wid = tid >> 5;
    const int lane = tid & 31;
    const int rowTile = blockIdx.x * 128;
    const int colTile = blockIdx.y * 128;
    const int warpM = wid & 3;
    const int warpN = wid >> 2;
    const int tg = lane & 3;

    float* c2s = (float*)(smem + SM_C2);
    if (tid < 128) c2s[tid] = g_c2f[colTile + tid];

    const int rowA = (lane & 7) + (((lane >> 3) & 1) << 3);
    const int koA  = ((lane >> 4) & 1) * 16;
    const int rowB = (lane & 7) + (((lane >> 4) & 1) << 3);
    const int koB  = ((lane >> 3) & 1) * 16;

    float acc[2][8][4];
    #pragma unroll
    for (int mt = 0; mt < 2; mt++)
        #pragma unroll
        for (int nt = 0; nt < 8; nt++)
            #pragma unroll
            for (int e = 0; e < 4; e++) acc[mt][nt][e] = 0.0f;

    stage_chunk(sbase, 0, rowTile, colTile, tid);
    stage_chunk(sbase, 1, rowTile, colTile, tid);

    #pragma unroll 1
    for (int c = 0; c < NCHUNK; c++) {
        if (c < NCHUNK - 1) CP_WAIT(1);
        else                CP_WAIT(0);
        __syncthreads();                 // chunk c visible; buffer (c+2)%3 drained
        if (c + 2 < NCHUNK)
            stage_chunk(sbase, c + 2, rowTile, colTile, tid);

        uint32_t abase = sbase + (c % 3) * STAGE_BYTES;
        uint32_t bbase = abase + 18432;

        #pragma unroll
        for (int ks = 0; ks < 4; ks++) {
            uint32_t a[2][4];
            #pragma unroll
            for (int mt = 0; mt < 2; mt++) {
                LDSM_X4(a[mt], abase + (warpM * 32 + mt * 16 + rowA) * PITCH
                               + ks * 32 + koA);
            }
            uint32_t b[8][2];
            #pragma unroll
            for (int nt2 = 0; nt2 < 4; nt2++) {
                uint32_t t[4];
                LDSM_X4(t, bbase + (warpN * 64 + nt2 * 16 + rowB) * PITCH
                           + ks * 32 + koB);
                b[2 * nt2][0]     = t[0];
                b[2 * nt2][1]     = t[1];
                b[2 * nt2 + 1][0] = t[2];
                b[2 * nt2 + 1][1] = t[3];
            }
            #pragma unroll
            for (int mt = 0; mt < 2; mt++)
                #pragma unroll
                for (int nt = 0; nt < 8; nt++)
                    mma16816(acc[mt][nt], a[mt], b[nt]);
        }
    }

    const int g = lane >> 2;
    const int slot = blockIdx.y * 2 + warpN;
    #pragma unroll
    for (int mt = 0; mt < 2; mt++) {
        #pragma unroll
        for (int rr = 0; rr < 2; rr++) {
            float v1 = FLT_MAX, v2 = FLT_MAX;
            int i1 = 0x7fffffff, i2 = 0x7fffffff;
            #pragma unroll
            for (int nt = 0; nt < 8; nt++) {
                #pragma unroll
                for (int e = 0; e < 2; e++) {
                    int colL = warpN * 64 + nt * 8 + tg * 2 + e;
                    float s = c2s[colL] - 2.0f * acc[mt][nt][rr * 2 + e];
                    int col = colTile + colL;
                    if (vi_lt(s, col, v1, i1)) { v2 = v1; i2 = i1; v1 = s; i1 = col; }
                    else if (vi_lt(s, col, v2, i2)) { v2 = s; i2 = col; }
                }
            }
            #pragma unroll
            for (int o = 1; o <= 2; o <<= 1) {
                float w1 = __shfl_xor_sync(0xffffffffu, v1, o);
                float w2 = __shfl_xor_sync(0xffffffffu, v2, o);
                int   j1 = __shfl_xor_sync(0xffffffffu, i1, o);
                int   j2 = __shfl_xor_sync(0xffffffffu, i2, o);
                if (vi_lt(w1, j1, v1, i1)) {
                    if (vi_lt(v1, i1, w2, j2)) { v2 = v1; i2 = i1; }
                    else                        { v2 = w2; i2 = j2; }
                    v1 = w1; i1 = j1;
                } else if (vi_lt(w1, j1, v2, i2)) {
                    v2 = w1; i2 = j1;
                }
            }
            if (tg == 0) {
                int rowL = warpM * 32 + mt * 16 + rr * 8 + g;
                size_t off = (size_t)slot * NPTS + rowTile + rowL;
                g_pv1[off] = v1; g_pi1[off] = i1;
                g_pv2[off] = v2; g_pi2[off] = i2;
            }
        }
    }
}

// ================= fused reduce + assign (queue close calls) ===================
// Threshold 4e-3 covers reference fp32 rounding (<=1.2e-4) plus fp16 x/c
// rounding in the GEMM score (sigma ~4.5e-4; ~9-sigma margin).
__global__ void reduce_assign_kernel(float* __restrict__ out_assign) {
    int n = blockIdx.x * 256 + threadIdx.x;
    if (n >= NPTS) return;
    float v1 = g_pv1[n], v2 = g_pv2[n];
    int i1 = g_pi1[n], i2 = g_pi2[n];
    #pragma unroll
    for (int p = 1; p < NSLOT; p++) {
        size_t off = (size_t)p * NPTS + n;
        float w1 = g_pv1[off], w2 = g_pv2[off];
        int j1 = g_pi1[off], j2 = g_pi2[off];
        if (vi_lt(w1, j1, v1, i1)) {
            if (vi_lt(v1, i1, w2, j2)) { v2 = v1; i2 = i1; }
            else                        { v2 = w2; i2 = j2; }
            v1 = w1; i1 = j1;
        } else if (vi_lt(w1, j1, v2, i2)) {
            v2 = w1; i2 = j1;
        }
    }
    if (v2 - v1 > 4e-3f) {
        g_assign[n] = i1;
        out_assign[n] = (float)i1;
        atomicAdd(&g_counts[i1], 1);
    } else {
        g_i1[n] = i1;
        g_i2[n] = i2;
        int pos = atomicAdd(&g_qcnt, 1);
        g_queue[pos] = n;
    }
}

// ================= fp64 refine on queued points only =================
__global__ void refine_queue_kernel(const float* __restrict__ x,
                                    const float* __restrict__ cent,
                                    float* __restrict__ out_assign)
{
    int warp = (blockIdx.x * blockDim.x + threadIdx.x) >> 5;
    int lane = threadIdx.x & 31;
    int nwarps = (gridDim.x * blockDim.x) >> 5;
    int qn = g_qcnt;

    for (int qi = warp; qi < qn; qi += nwarps) {
        int n = g_queue[qi];
        int i1 = g_i1[n], i2 = g_i2[n];

        const float4* xr = (const float4*)(x + (size_t)n * DD);
        float4 xa = xr[lane], xb = xr[lane + 32];
        const float4* c1 = (const float4*)(cent + (size_t)i1 * DD);
        float4 ca = c1[lane], cb = c1[lane + 32];
        const float4* c2p = (const float4*)(cent + (size_t)i2 * DD);
        float4 da = c2p[lane], db = c2p[lane + 32];

        double x2 = (double)xa.x * xa.x + (double)xa.y * xa.y +
                    (double)xa.z * xa.z + (double)xa.w * xa.w +
                    (double)xb.x * xb.x + (double)xb.y * xb.y +
                    (double)xb.z * xb.z + (double)xb.w * xb.w;
        double m1 = (double)xa.x * ca.x + (double)xa.y * ca.y +
                    (double)xa.z * ca.z + (double)xa.w * ca.w +
                    (double)xb.x * cb.x + (double)xb.y * cb.y +
                    (double)xb.z * cb.z + (double)xb.w * cb.w;
        double m2 = (double)xa.x * da.x + (double)xa.y * da.y +
                    (double)xa.z * da.z + (double)xa.w * da.w +
                    (double)xb.x * db.x + (double)xb.y * db.y +
                    (double)xb.z * db.z + (double)xb.w * db.w;

        #pragma unroll
        for (int o = 16; o; o >>= 1) {
            x2 += __shfl_xor_sync(0xffffffffu, x2, o);
            m1 += __shfl_xor_sync(0xffffffffu, m1, o);
            m2 += __shfl_xor_sync(0xffffffffu, m2, o);
        }

        if (lane == 0) {
            float x2f = (float)x2, m1f = (float)m1, m2f = (float)m2;
            float d2a = __fadd_rn(__fsub_rn(x2f, __fmul_rn(2.0f, m1f)), g_c2f[i1]);
            float d2b = __fadd_rn(__fsub_rn(x2f, __fmul_rn(2.0f, m2f)), g_c2f[i2]);
            d2a = fmaxf(d2a, 0.0f);
            d2b = fmaxf(d2b, 0.0f);
            float dsa = __fsqrt_rn(d2a);
            float dsb = __fsqrt_rn(d2b);
            int win;
            if (dsa < dsb)      win = i1;
            else if (dsb < dsa) win = i2;
            else                win = (i1 < i2) ? i1 : i2;
            g_assign[n] = win;
            out_assign[n] = (float)win;
            atomicAdd(&g_counts[win], 1);
        }
    }
}

// ================= binning: scan counts -> per-cluster lists =================
__global__ void offsets_kernel() {
    __shared__ int sh[KC];
    int t = threadIdx.x;  // 512
    int c = g_counts[t];
    sh[t] = c;
    __syncthreads();
    #pragma unroll
    for (int o = 1; o < KC; o <<= 1) {
        int v = (t >= o) ? sh[t - o] : 0;
        __syncthreads();
        sh[t] += v;
        __syncthreads();
    }
    int excl = sh[t] - c;
    g_offs[t] = excl;
    g_cursor[t] = excl;
}

__global__ void fill_kernel() {
    int n = blockIdx.x * 256 + threadIdx.x;
    if (n >= NPTS) return;
    int a = g_assign[n];
    int pos = atomicAdd(&g_cursor[a], 1);
    g_order[pos] = n;
}

// ================= per-cluster sum (no atomics) + finalize =================
__global__ void sum_finalize_kernel(const float* __restrict__ x,
                                    const float* __restrict__ cent,
                                    float* __restrict__ out_old,
                                    float* __restrict__ out_new)
{
    int k = blockIdx.x;
    int d = threadIdx.x;  // 256
    int beg = g_offs[k];
    int cnt = g_counts[k];

    float acc = 0.0f;
    int i = 0;
    for (; i + 4 <= cnt; i += 4) {
        int p0 = g_order[beg + i];
        int p1 = g_order[beg + i + 1];
        int p2 = g_order[beg + i + 2];
        int p3 = g_order[beg + i + 3];
        acc += x[(size_t)p0 * DD + d];
        acc += x[(size_t)p1 * DD + d];
        acc += x[(size_t)p2 * DD + d];
        acc += x[(size_t)p3 * DD + d];
    }
    for (; i < cnt; i++) {
        int p = g_order[beg + i];
        acc += x[(size_t)p * DD + d];
    }

    int idx = k * DD + d;
    float oldv = cent[idx];
    out_old[idx] = oldv;
    out_new[idx] = (cnt > 0) ? (acc / (float)cnt) : oldv;
}

// ================= launch =================
extern "C" void kernel_launch(void* const* d_in, const int* in_sizes, int n_in,
                              void* d_out, int out_size) {
    const float* x = (const float*)d_in[0];
    const float* cent = (const float*)d_in[1];
    float* out = (float*)d_out;

    float* out_old;
    float* out_assign;
    float* out_new;
    float* p_dummy_kd = nullptr;
    float* p_dummy_n = nullptr;
    cudaGetSymbolAddress((void**)&p_dummy_kd, g_dummy_kd);
    cudaGetSymbolAddress((void**)&p_dummy_n, g_dummy_n);

    if (out_size >= KC * DD + NPTS + KC * DD) {
        out_old = out;
        out_assign = out + KC * DD;
        out_new = out_assign + NPTS;
    } else if (out_size == NPTS + KC * DD) {
        out_old = p_dummy_kd;
        out_assign = out;
        out_new = out + NPTS;
    } else if (out_size == KC * DD) {
        out_old = p_dummy_kd;
        out_assign = p_dummy_n;
        out_new = out;
    } else {
        out_old = p_dummy_kd;
        out_assign = p_dummy_n;
        out_new = p_dummy_kd;
    }

    cudaFuncSetAttribute(mma_top2_kernel,
                         cudaFuncAttributeMaxDynamicSharedMemorySize, SM_TOTAL);

    c2z_kernel<<<KC, 64>>>(cent);                                  // 1
    convert_x_kernel<<<(NPTS * (DD / 4)) / 256, 256>>>(x);         // 2
    convert_c_kernel<<<(KC * (DD / 4) + 255) / 256, 256>>>(cent);  // 3
    {
        dim3 grid(NPTS / 128, 4);
        mma_top2_kernel<<<grid, 256, SM_TOTAL>>>();                // 4 (ncu slot)
    }
    reduce_assign_kernel<<<NPTS / 256, 256>>>(out_assign);         // 5
    refine_queue_kernel<<<256, 256>>>(x, cent, out_assign);        // 6
    offsets_kernel<<<1, KC>>>();                                   // 7
    fill_kernel<<<NPTS / 256, 256>>>();                            // 8
    sum_finalize_kernel<<<KC, DD>>>(x, cent, out_old, out_new);    // 9
}